// round 3
// baseline (speedup 1.0000x reference)
#include <cuda_runtime.h>

// Problem constants (from reference)
#define TT    64
#define NB    16
#define CC    256
#define DOUT  129
#define THREADS 256

// DECAY = exp(-0.5); P[k] = DECAY^k = 2^(-k * 0.5*log2(e))
#define LOG2E_HALF 0.72134752044448169f

__global__ __launch_bounds__(THREADS, 8)
void jeffress_kernel(const float2* __restrict__ inp,         // (T, N*C) as float2 over last dim
                     const float*  __restrict__ delay_param, // (129)
                     const float*  __restrict__ weight,      // scalar
                     const float2* __restrict__ u,           // (N*C, 129) as float2 over last dim
                     float*        __restrict__ out)         // (T, N*C, 129)
{
    __shared__ float xs[2][64];
    __shared__ float S[2][64];
    __shared__ float P[66];
    __shared__ float C1s[2][DOUT];
    __shared__ float C2s[2][DOUT];
    __shared__ int   dtab[DOUT];
    __shared__ int   Lsh[2];
    __shared__ float S63sh[2];

    const int tid = threadIdx.x;
    const int bid = blockIdx.x;   // n*C + c

    // ---- load the 64-step time series for both channels (8B per t, L2-friendly) ----
    if (tid < 64) {
        float2 v = inp[tid * (NB * CC) + bid];
        xs[0][tid] = v.x;
        xs[1][tid] = v.y;
    }
    // ---- decay-power table in parallel (warp 1+, no dependency on xs) ----
    if (tid >= 32 && tid < 32 + 66) {
        int k = tid - 32;
        P[k] = exp2f(-LOG2E_HALF * (float)k);
    }
    __syncthreads();

    // ---- serial LIF prefix scan + first-argmax, one channel per lane (lanes 0,1) ----
    if (tid < 2) {
        const float a = 0.60653065971263342f; // exp(-0.5)
        float v = 0.f;
        float best = -1.f;
        int bt = 0;
        #pragma unroll
        for (int t = 0; t < 64; t++) {
            float x = xs[tid][t];
            v = v * a + x;
            S[tid][t] = v;
            if (x > best) { best = x; bt = t; }   // strict '>' keeps FIRST max (jnp.argmax)
        }
        Lsh[tid]   = 63 - bt;   // clamp limit (T-1 - spike_t)
        S63sh[tid] = v;         // S[63]
    }
    __syncthreads();

    // ---- per-delay tables: clamped integer shift d, C1 = S63*a^-d - S[63-d], C2 = -S[63-d] ----
    if (tid < DOUT) {
        const int dd = tid;
        const float dp = delay_param[dd];
        const float2 uu = u[bid * DOUT + dd];
        int dpack = 0;
        #pragma unroll
        for (int ch = 0; ch < 2; ch++) {
            float delay = fmaxf(ch == 0 ? dp : -dp, 0.f);   // relu(+/- delay_param)
            float df    = floorf(delay);
            float uv    = (ch == 0) ? uu.x : uu.y;
            float r     = (uv < delay - df) ? df + 1.f : df; // stochastic rounding (degenerate here)
            float rc    = fminf(r, (float)Lsh[ch]);          // clamp so spike stays in window
            int d = (int)rc;
            d = max(0, min(63, d));
            float S63md = S[ch][63 - d];
            C1s[ch][dd] = fmaf(S63sh[ch], exp2f(LOG2E_HALF * (float)d), -S63md);
            C2s[ch][dd] = -S63md;
            dpack |= d << (8 * ch);
        }
        dtab[dd] = dpack;
    }
    __syncthreads();

    // ---- emit all 64*129 outputs for this (n,c): f(t,d) = S[(t-d)&63] + P[t+1]*Csel ----
    const float W = *weight;
    float* outb = out + (size_t)bid * DOUT;

    for (int e = tid; e < TT * DOUT; e += THREADS) {
        unsigned ue = (unsigned)e;
        unsigned t  = ue / DOUT;           // constant division -> mul+shift
        unsigned dd = ue - t * DOUT;
        int   it  = (int)t;
        float pt1 = P[t + 1];
        int dp2 = dtab[dd];
        int d0  = dp2 & 255;
        int d1  = dp2 >> 8;
        int q0  = (it - d0) & 63;
        int q1  = (it - d1) & 63;
        float c0 = (it >= d0) ? C1s[0][dd] : C2s[0][dd];
        float c1 = (it >= d1) ? C1s[1][dd] : C2s[1][dd];
        float f0 = fmaf(pt1, c0, S[0][q0]);
        float f1 = fmaf(pt1, c1, S[1][q1]);
        outb[(size_t)t * (NB * CC * DOUT) + dd] = (f0 + f1) * W;
    }
}

extern "C" void kernel_launch(void* const* d_in, const int* in_sizes, int n_in,
                              void* d_out, int out_size)
{
    // Defensive pointer mapping by element count (metadata order: input, delay_param, weight, u)
    const void* p_input = d_in[0];
    const void* p_delay = d_in[1];
    const void* p_w     = d_in[2];
    const void* p_u     = d_in[3];
    for (int i = 0; i < n_in; i++) {
        if (in_sizes[i] == TT * NB * CC * 2)       p_input = d_in[i];
        else if (in_sizes[i] == DOUT)              p_delay = d_in[i];
        else if (in_sizes[i] == 1)                 p_w     = d_in[i];
        else if (in_sizes[i] == NB * CC * DOUT * 2) p_u    = d_in[i];
    }

    jeffress_kernel<<<NB * CC, THREADS>>>(
        (const float2*)p_input,
        (const float*)p_delay,
        (const float*)p_w,
        (const float2*)p_u,
        (float*)d_out);
}

// round 5
// speedup vs baseline: 1.3351x; 1.3351x over previous
#include <cuda_runtime.h>

// Problem constants
#define TT      64
#define NB      16
#define CC      256
#define DOUT    129
#define THREADS 160                      // 5 warps; threads 0..128 active in emit
#define TSTRIDE (NB * CC * DOUT)         // float stride between consecutive t in out

#define LOG2E_HALF 0.72134752044448169f  // 0.5*log2(e); a^k = 2^(-k*LOG2E_HALF)

__global__ __launch_bounds__(THREADS, 6)
void jeffress_kernel(const float2* __restrict__ inp,         // (T, N*C) float2 over last dim
                     const float*  __restrict__ delay_param, // (129)
                     const float*  __restrict__ weight,      // scalar
                     const float2* __restrict__ u,           // (N*C, 129) float2 over last dim
                     float*        __restrict__ out)         // (T, N*C, 129)
{
    __shared__ float xs[2][64];
    __shared__ float S[2][64];
    __shared__ float P[66];
    __shared__ float U2[2][192];   // [64+q]=S[q]*W ; [128+q]=(S[q]+P[q+1]*S63)*W
    __shared__ int   Lsh[2];
    __shared__ float S63sh[2];

    const int tid = threadIdx.x;
    const int bid = blockIdx.x;    // n*C + c

    // ---- load the 64-step series for both channels ----
    if (tid < 64) {
        float2 v = inp[tid * (NB * CC) + bid];
        xs[0][tid] = v.x;
        xs[1][tid] = v.y;
    }
    // ---- decay-power table (independent warps) ----
    if (tid >= 64 && tid < 64 + 65) {
        int k = tid - 64;
        P[k] = exp2f(-LOG2E_HALF * (float)k);
    }
    __syncthreads();

    // ---- serial LIF prefix scan + FIRST argmax, one channel per lane ----
    if (tid < 2) {
        const float a = 0.60653065971263342f; // exp(-0.5)
        float v = 0.f, best = -1.f;
        int bt = 0;
        #pragma unroll
        for (int t = 0; t < 64; t++) {
            float x = xs[tid][t];
            v = v * a + x;
            S[tid][t] = v;
            if (x > best) { best = x; bt = t; }   // strict '>' => first max
        }
        Lsh[tid]   = 63 - bt;
        S63sh[tid] = v;
    }
    __syncthreads();

    const float W = *weight;

    // ---- build unwrapped, W-prescaled tables U2 ----
    for (int i = tid; i < 2 * 64; i += THREADS) {
        int ch = i >> 6, q = i & 63;
        float sv = S[ch][q];
        U2[ch][64 + q]  = sv * W;                              // t < d regime
        U2[ch][128 + q] = fmaf(P[q + 1], S63sh[ch], sv) * W;   // t >= d regime
    }
    __syncthreads();

    // ---- emit: one thread per delay index dd ----
    if (tid < DOUT) {
        const int dd = tid;
        const float  dp = delay_param[dd];
        const float2 uu = u[(size_t)bid * DOUT + dd];

        int dch[2];
        float ncm = 0.f;
        #pragma unroll
        for (int ch = 0; ch < 2; ch++) {
            float delay = fmaxf(ch == 0 ? dp : -dp, 0.f);      // relu(+/- delay_param)
            float df    = floorf(delay);
            float uv    = (ch == 0) ? uu.x : uu.y;
            float r     = (uv < delay - df) ? df + 1.f : df;   // stochastic rounding
            float rc    = fminf(r, (float)Lsh[ch]);            // clamp to window
            int   di    = (int)rc;
            di = di < 0 ? 0 : (di > 63 ? 63 : di);
            dch[ch] = di;
            ncm += S[ch][63 - di];
        }
        ncm = -ncm * W;   // f = U0[j0] + U1[j1] + a^{t+1} * ncm

        const float* U0p = &U2[0][128 - dch[0]];  // index by t, linear, no wrap
        const float* U1p = &U2[1][128 - dch[1]];
        float* outp = out + (size_t)bid * DOUT + dd;

        const float a  = 0.60653065971263342f;
        const float a2 = a * a, a3 = a2 * a, a4 = a2 * a2;
        // pt1(t4+k) = a^{t4+k+1} = ptb * a^{k+1}, ptb = a^{t4}
        const float n0 = ncm * a, n1 = ncm * a2, n2 = ncm * a3, n3 = ncm * a4;
        float ptb = 1.0f;

        #pragma unroll
        for (int t4 = 0; t4 < 64; t4 += 4) {
            float s0 = U0p[t4 + 0] + U1p[t4 + 0];
            float s1 = U0p[t4 + 1] + U1p[t4 + 1];
            float s2 = U0p[t4 + 2] + U1p[t4 + 2];
            float s3 = U0p[t4 + 3] + U1p[t4 + 3];
            outp[0]                     = fmaf(ptb, n0, s0);
            outp[(size_t)TSTRIDE]       = fmaf(ptb, n1, s1);
            outp[(size_t)(2 * TSTRIDE)] = fmaf(ptb, n2, s2);
            outp[(size_t)(3 * TSTRIDE)] = fmaf(ptb, n3, s3);
            ptb *= a4;
            outp += 4 * (size_t)TSTRIDE;
        }
    }
}

extern "C" void kernel_launch(void* const* d_in, const int* in_sizes, int n_in,
                              void* d_out, int out_size)
{
    const void* p_input = d_in[0];
    const void* p_delay = d_in[1];
    const void* p_w     = d_in[2];
    const void* p_u     = d_in[3];
    for (int i = 0; i < n_in; i++) {
        if (in_sizes[i] == TT * NB * CC * 2)        p_input = d_in[i];
        else if (in_sizes[i] == DOUT)               p_delay = d_in[i];
        else if (in_sizes[i] == 1)                  p_w     = d_in[i];
        else if (in_sizes[i] == NB * CC * DOUT * 2) p_u     = d_in[i];
    }

    jeffress_kernel<<<NB * CC, THREADS>>>(
        (const float2*)p_input,
        (const float*)p_delay,
        (const float*)p_w,
        (const float2*)p_u,
        (float*)d_out);
}

// round 8
// speedup vs baseline: 1.3487x; 1.0101x over previous
#include <cuda_runtime.h>

#define TT      64
#define NB      16
#define CC      256
#define DOUT    129
#define THREADS 128
#define TSTRIDE (NB * CC * DOUT)          // floats between consecutive t planes

#define LOG2E_HALF 0.72134752044448169f   // 0.5*log2(e); a^k = 2^(-k*LOG2E_HALF)

// Shift-copy placement (floats) inside each channel's table.
// pos[s] mod 32 = {20, 0, 8, 16} for s = {0,1,2,3}  -> bank-conflict-free LDS.128
__device__ __forceinline__ int copy_pos(int s) {
    return (s == 0) ? 628 : (s * 200 - 200);   // s=1->0, s=2->200, s=3->400, s=0->628
}

__global__ __launch_bounds__(THREADS, 10)
void jeffress_kernel(const float2* __restrict__ inp,         // (T, N*C) float2 over last dim
                     const float*  __restrict__ delay_param, // (129)
                     const float*  __restrict__ weight,      // scalar
                     const float2* __restrict__ u,           // (N*C, 129) float2 over last dim
                     float*        __restrict__ out)         // (T, N*C, 129)
{
    __shared__ float xs[2][64];
    __shared__ float S[2][64];
    __shared__ float P[65];
    __shared__ __align__(16) float Ctab[2][832];  // 4 shifted copies of U-table per channel
    __shared__ int   Lsh[2];
    __shared__ float S63sh[2];

    const int tid = threadIdx.x;
    const int bid = blockIdx.x;     // n*C + c

    // ---- prefetch per-thread inputs early (hide LDG latency behind prologue) ----
    const float  dp = delay_param[tid];                 // tid < 128 < DOUT
    const float2 uu = u[(size_t)bid * DOUT + tid];

    // ---- stage the 64-step time series (both channels) ----
    if (tid < 64) {
        float2 v = inp[tid * (NB * CC) + bid];
        xs[0][tid] = v.x;
        xs[1][tid] = v.y;
    }
    // ---- decay powers P[k] = a^k, k in [0,64] (threads 63..127) ----
    if (tid >= 63) {
        int k = tid - 63;
        P[k] = exp2f(-LOG2E_HALF * (float)k);
    }
    __syncthreads();

    // ---- serial LIF prefix scan + FIRST argmax, one channel per lane ----
    if (tid < 2) {
        const float a = 0.60653065971263342f;  // exp(-0.5)
        float v = 0.f, best = -1.f;
        int bt = 0;
        #pragma unroll
        for (int t = 0; t < 64; t++) {
            float x = xs[tid][t];
            v = v * a + x;
            S[tid][t] = v;
            if (x > best) { best = x; bt = t; }   // strict '>' => first max (jnp.argmax)
        }
        Lsh[tid]   = 63 - bt;
        S63sh[tid] = v;
    }
    __syncthreads();

    const float W = *weight;

    // ---- build 4 shift-aligned copies per channel:
    //      Ctab[ch][pos[s] + i] = U(i+s), where
    //      U(q) = S[q-64]*W                      for 65 <= q < 128   (t <  d regime)
    //      U(q) = (S[q-128] + P[q-127]*S63)*W    for 128 <= q < 192  (t >= d regime)
    #pragma unroll
    for (int cs = 0; cs < 8; cs++) {
        const int ch = cs >> 2, s = cs & 3;
        const int pos = copy_pos(s);
        const float S63 = S63sh[ch];
        for (int i = 62 + tid; i < 192; i += THREADS) {
            int q = i + s;
            float v = 0.f;
            if (q >= 65 && q < 128)        v = S[ch][q - 64] * W;
            else if (q >= 128 && q < 192)  v = fmaf(P[q - 127], S63, S[ch][q - 128]) * W;
            Ctab[ch][pos + i] = v;
        }
    }
    __syncthreads();

    // ---- per-thread constants for dd = tid ----
    const float L0 = (float)Lsh[0], L1 = (float)Lsh[1];
    float del0 = fmaxf(dp, 0.f),  del1 = fmaxf(-dp, 0.f);   // relu(+/- delay_param)
    float df0  = floorf(del0),    df1  = floorf(del1);
    float r0 = (uu.x < del0 - df0) ? df0 + 1.f : df0;       // stochastic rounding
    float r1 = (uu.y < del1 - df1) ? df1 + 1.f : df1;
    r0 = fminf(r0, L0);  r1 = fminf(r1, L1);                // clamp to window
    const int d0 = min(63, max(0, (int)r0));
    const int d1 = min(63, max(0, (int)r1));
    const float ncm = -(S[0][63 - d0] + S[1][63 - d1]) * W;

    const int s0 = (-d0) & 3, s1 = (-d1) & 3;
    const int bi0 = copy_pos(s0) + (128 - d0 - s0);   // multiple of 4 -> 16B aligned
    const int bi1 = copy_pos(s1) + (128 - d1 - s1);
    const float4* A4 = (const float4*)&Ctab[0][bi0];
    const float4* B4 = (const float4*)&Ctab[1][bi1];

    const float a  = 0.60653065971263342f;
    const float a2 = a * a, a3 = a2 * a, a4 = a2 * a2;
    const float n0 = ncm * a, n1 = ncm * a2, n2 = ncm * a3, n3 = ncm * a4;
    float ptb = 1.0f;                                  // a^{4g}
    float* outp = out + (size_t)bid * DOUT + tid;

    // ---- emit 64 outputs: f(t) = U0[..+t] + U1[..+t] + a^{t+1}*ncm ----
    #pragma unroll 2
    for (int g = 0; g < 16; g++) {
        float4 A = A4[g];
        float4 B = B4[g];
        __stcs(outp,               fmaf(ptb, n0, A.x + B.x));
        __stcs(outp + TSTRIDE,     fmaf(ptb, n1, A.y + B.y));
        __stcs(outp + 2 * TSTRIDE, fmaf(ptb, n2, A.z + B.z));
        __stcs(outp + 3 * TSTRIDE, fmaf(ptb, n3, A.w + B.w));
        ptb *= a4;
        outp += 4 * TSTRIDE;
    }

    // ---- tail: dd = 128, one t per thread (threads 0..63) ----
    if (tid < 64) {
        const float  dpL = delay_param[DOUT - 1];
        const float2 uL  = u[(size_t)bid * DOUT + (DOUT - 1)];
        float e0f = fmaxf(dpL, 0.f), e1f = fmaxf(-dpL, 0.f);
        float f0  = floorf(e0f),     f1  = floorf(e1f);
        float q0 = (uL.x < e0f - f0) ? f0 + 1.f : f0;
        float q1 = (uL.y < e1f - f1) ? f1 + 1.f : f1;
        q0 = fminf(q0, L0);  q1 = fminf(q1, L1);
        const int e0 = min(63, max(0, (int)q0));
        const int e1 = min(63, max(0, (int)q1));
        const float nc = -(S[0][63 - e0] + S[1][63 - e1]) * W;
        const int t = tid;
        // copy s=1 sits at pos 0: Ctab[ch][i] = U(i+1)  -> read i = (128-e+t) - 1
        float v0 = Ctab[0][127 - e0 + t];
        float v1 = Ctab[1][127 - e1 + t];
        __stcs(out + (size_t)t * TSTRIDE + (size_t)bid * DOUT + 128,
               fmaf(P[t + 1], nc, v0 + v1));
    }
}

extern "C" void kernel_launch(void* const* d_in, const int* in_sizes, int n_in,
                              void* d_out, int out_size)
{
    const void* p_input = d_in[0];
    const void* p_delay = d_in[1];
    const void* p_w     = d_in[2];
    const void* p_u     = d_in[3];
    for (int i = 0; i < n_in; i++) {
        if (in_sizes[i] == TT * NB * CC * 2)        p_input = d_in[i];
        else if (in_sizes[i] == DOUT)               p_delay = d_in[i];
        else if (in_sizes[i] == 1)                  p_w     = d_in[i];
        else if (in_sizes[i] == NB * CC * DOUT * 2) p_u     = d_in[i];
    }

    jeffress_kernel<<<NB * CC, THREADS>>>(
        (const float2*)p_input,
        (const float*)p_delay,
        (const float*)p_w,
        (const float2*)p_u,
        (float*)d_out);
}